// round 12
// baseline (speedup 1.0000x reference)
#include <cuda_runtime.h>
#include <math.h>

// Problem constants
#define N        10000
#define DF       32
#define ITERS    4
#define JSPLIT   18             // j-range splits
#define PCHUNK   285            // packed j-pairs per split (570 j), 57*5
#define NPAIR_PAD (JSPLIT * PCHUNK)    // 5130 pairs = 10260 j slots
#define NSLOTS_J (2 * NPAIR_PAD)       // 10260
#define ITILE    256
#define NITILE   40             // i-slots 10240; grid 40*18=720, 1 wave @ occ 5
#define NSLOTS_I 10240
#define ZSCALE   16384.0f
#define SENTC    1.0e6f

// Scratch (static device arrays; cudaMalloc is forbidden)
__device__ float g_pairsA[NPAIR_PAD * 16];
__device__ float g_pairsB[NPAIR_PAD * 16];
__device__ int   g_cnt[ITERS * NITILE];        // stripe completion counters
__device__ float g_part[JSPLIT * NSLOTS_I * 12];
__device__ float g_h[ITERS * N * DF];
__device__ float g_w[ITERS * N * 3];

// ---------------------------------------------------------------------------
// Pair record (16 words per packed j-pair):
//   [0..7]  x0 x1 y0 y1 z0 z1 nu0 nu1   (nu = -0.5|x|^2)
//   [8..11] x0 y0 x1 y1                  (xy addends)
//   [12,13] round(z*2^14) s32            (z fixed-point)
// ---------------------------------------------------------------------------
__device__ __forceinline__ void write_rec(float* buf, int s, float x, float y, float z) {
    int p = s >> 1, h = s & 1;
    float nu = -0.5f * (x * x + y * y + z * z);
    float* rec = buf + p * 16;
    rec[0 + h] = x;
    rec[2 + h] = y;
    rec[4 + h] = z;
    rec[6 + h] = nu;
    rec[8 + 2 * h] = x;
    rec[9 + 2 * h] = y;
    ((int*)rec)[12 + h] = __float2int_rn(z * ZSCALE);
}

// ---------------------------------------------------------------------------
// linear1: h = X_fea @ W1^T + b1 for all 4 iterations
// ---------------------------------------------------------------------------
__global__ void linear1_kernel(const float* __restrict__ Xfea,
                               const float* __restrict__ W1,
                               const float* __restrict__ b1) {
    int it = blockIdx.y;
    int n  = blockIdx.x * blockDim.x + threadIdx.x;
    __shared__ float sW[DF * DF];
    __shared__ float sb[DF];
    for (int k = threadIdx.x; k < DF * DF; k += blockDim.x) sW[k] = W1[it * DF * DF + k];
    if (threadIdx.x < DF) sb[threadIdx.x] = b1[it * DF + threadIdx.x];
    __syncthreads();
    if (n >= N) return;
    float xf[DF];
    const float4* xr = (const float4*)(Xfea + n * DF);
    #pragma unroll
    for (int q = 0; q < DF / 4; q++) {
        float4 v = xr[q];
        xf[4*q] = v.x; xf[4*q+1] = v.y; xf[4*q+2] = v.z; xf[4*q+3] = v.w;
    }
    float* hout = g_h + (it * N + n) * DF;
    #pragma unroll 4
    for (int f = 0; f < DF; f++) {
        float acc = sb[f];
        #pragma unroll
        for (int k = 0; k < DF; k++) acc = fmaf(xf[k], sW[f * DF + k], acc);
        hout[f] = acc;
    }
}

// BN stats + BN/ReLU/linear2/exp + pair-record prep + counters. Block = iter.
__global__ void __launch_bounds__(1024, 1) bnlogits_prep_kernel(
        const float* __restrict__ X,
        const float* __restrict__ gamma,
        const float* __restrict__ beta,
        const float* __restrict__ W2,
        const float* __restrict__ b2) {
    int it = blockIdx.x;
    int tid = threadIdx.x;
    int w  = tid >> 5;
    int f  = tid & 31;
    __shared__ float ss[32 * 33];
    __shared__ float sqq[32 * 33];
    __shared__ float smu[DF], sis[DF], sg[DF], sbe[DF], sW2[3 * DF], sb2[3];

    float s = 0.f, sq = 0.f;
    for (int n = w; n < N; n += 32) {
        float v = g_h[(it * N + n) * DF + f];
        s += v;
        sq = fmaf(v, v, sq);
    }
    ss [w * 33 + f] = s;
    sqq[w * 33 + f] = sq;
    if (tid < DF) { sg[tid] = gamma[it * DF + tid]; sbe[tid] = beta[it * DF + tid]; }
    if (tid < 3 * DF) sW2[tid] = W2[it * 3 * DF + tid];
    if (tid < 3)      sb2[tid] = b2[it * 3 + tid];
    __syncthreads();
    if (tid < DF) {
        float ts = 0.f, tq = 0.f;
        for (int ww = 0; ww < 32; ww++) { ts += ss[ww * 33 + f]; tq += sqq[ww * 33 + f]; }
        float mu  = ts / (float)N;
        float var = tq / (float)N - mu * mu;   // biased var (matches reference)
        smu[tid] = mu;
        sis[tid] = rsqrtf(var + 1e-5f);
    }
    __syncthreads();

    for (int n = tid; n < N; n += 1024) {
        const float* hrow = g_h + (it * N + n) * DF;
        float l0 = sb2[0], l1 = sb2[1], l2 = sb2[2];
        #pragma unroll
        for (int k = 0; k < DF; k++) {
            float a = fmaxf((hrow[k] - smu[k]) * sis[k] * sg[k] + sbe[k], 0.f);
            l0 = fmaf(a, sW2[0 * DF + k], l0);
            l1 = fmaf(a, sW2[1 * DF + k], l1);
            l2 = fmaf(a, sW2[2 * DF + k], l2);
        }
        float m = fmaxf(l0, fmaxf(l1, l2));
        float* wout = g_w + (it * N + n) * 3;
        wout[0] = expf(l0 - m);
        wout[1] = expf(l1 - m);
        wout[2] = expf(l2 - m);
    }

    // fused prep across the 4 blocks (gtid 0..4095)
    int gtid = blockIdx.x * 1024 + tid;
    for (int sl = gtid; sl < NSLOTS_J; sl += 4096) {
        if (sl < N) write_rec(g_pairsA, sl, X[3*sl], X[3*sl+1], X[3*sl+2]);
        else        write_rec(g_pairsA, sl, SENTC, SENTC, SENTC);
        // B buffer tail (>= NSLOTS_I) is never rewritten by shift: fill once.
        if (sl >= NSLOTS_I) write_rec(g_pairsB, sl, SENTC, SENTC, SENTC);
    }
    if (gtid < ITERS * NITILE) g_cnt[gtid] = 0;
}

// ---------------------------------------------------------------------------
// Mean-shift pair loop (R4 body, LDS.128 tile reads) + fused finalize.
// ---------------------------------------------------------------------------
__global__ void __launch_bounds__(ITILE, 5) shift_kernel(float* __restrict__ out, int it) {
    __shared__ __align__(16) float sj[PCHUNK * 16];   // 18.2 KB tile
    __shared__ int s_last;

    const float* srcP = (it & 1) ? g_pairsB : g_pairsA;
    float*       dstP = (it & 1) ? g_pairsA : g_pairsB;

    int js  = blockIdx.y;
    int bx  = blockIdx.x;
    int tid = threadIdx.x;

    const float4* src = (const float4*)(srcP + js * PCHUNK * 16);
    float4* d4 = (float4*)sj;
    for (int t = tid; t < PCHUNK * 4; t += ITILE) d4[t] = src[t];
    __syncthreads();

    int slot = bx * ITILE + tid;     // < NSLOTS_I <= NSLOTS_J
    int pb = (slot >> 1) * 16, h = slot & 1;
    float xi  = srcP[pb + 0 + h];
    float yi  = srcP[pb + 2 + h];
    float zi  = srcP[pb + 4 + h];
    float nui = srcP[pb + 6 + h];
    // d <= bw^2  <=>  (xi.xj - 0.5|xj|^2) >= 0.5|xi|^2 - 0.5 bw^2
    float th1 = -nui - 0.02f;    // bw=0.2
    float th2 = -nui - 1.445f;   // bw=1.7
    float th3 = -nui - 5.12f;    // bw=3.2

    unsigned long long xi2, yi2, zi2;
    asm("mov.b64 %0, {%1, %1};" : "=l"(xi2) : "f"(xi));
    asm("mov.b64 %0, {%1, %1};" : "=l"(yi2) : "f"(yi));
    asm("mov.b64 %0, {%1, %1};" : "=l"(zi2) : "f"(zi));

    unsigned long long axy1 = 0ull, axy2 = 0ull, axy3 = 0ull;  // (sumx,sumy)
    int   az1 = 0, az2 = 0, az3 = 0;                           // fixed-point z
    int   ac1 = 0, ac2 = 0;                                    // counts 1,2
    float fc3 = 0.0f;                                          // count 3

    const ulonglong2* tile = (const ulonglong2*)sj;
    #pragma unroll 5
    for (int p = 0; p < PCHUNK; p++) {
        ulonglong2 rA = tile[4 * p + 0];   // (x01,  y01)
        ulonglong2 rB = tile[4 * p + 1];   // (z01,  nu01)
        ulonglong2 rC = tile[4 * p + 2];   // (xy0,  xy1)
        ulonglong2 rD = tile[4 * p + 3];   // (zf01, pad)
        int zf0 = (int)(unsigned)rD.x;
        int zf1 = (int)(rD.x >> 32);
        asm("{\n\t"
            ".reg .b64  t64;\n\t"
            ".reg .f32  vl, vh;\n\t"
            ".reg .pred pl1, pl2, pl3, ph1, ph2, ph3;\n\t"
            "fma.rn.f32x2 t64, %9, %12, %15;\n\t"    // xi*xj - 0.5|xj|^2
            "fma.rn.f32x2 t64, %10, %13, t64;\n\t"
            "fma.rn.f32x2 t64, %11, %14, t64;\n\t"
            "mov.b64 {vl, vh}, t64;\n\t"
            "setp.ge.f32 pl1, vl, %16;\n\t"
            "setp.ge.f32 pl2, vl, %17;\n\t"
            "setp.ge.f32 pl3, vl, %18;\n\t"
            "setp.ge.f32 ph1, vh, %16;\n\t"
            "setp.ge.f32 ph2, vh, %17;\n\t"
            "setp.ge.f32 ph3, vh, %18;\n\t"
            "@pl1 add.rn.f32x2 %0, %0, %19;\n\t"
            "@pl1 add.s32 %3, %3, %21;\n\t"
            "@pl1 add.s32 %6, %6, 1;\n\t"
            "@pl2 add.rn.f32x2 %1, %1, %19;\n\t"
            "@pl2 add.s32 %4, %4, %21;\n\t"
            "@pl2 add.s32 %7, %7, 1;\n\t"
            "@pl3 add.rn.f32x2 %2, %2, %19;\n\t"
            "@pl3 add.s32 %5, %5, %21;\n\t"
            "@pl3 add.f32 %8, %8, 0F3F800000;\n\t"
            "@ph1 add.rn.f32x2 %0, %0, %20;\n\t"
            "@ph1 add.s32 %3, %3, %22;\n\t"
            "@ph1 add.s32 %6, %6, 1;\n\t"
            "@ph2 add.rn.f32x2 %1, %1, %20;\n\t"
            "@ph2 add.s32 %4, %4, %22;\n\t"
            "@ph2 add.s32 %7, %7, 1;\n\t"
            "@ph3 add.rn.f32x2 %2, %2, %20;\n\t"
            "@ph3 add.s32 %5, %5, %22;\n\t"
            "@ph3 add.f32 %8, %8, 0F3F800000;\n\t"
            "}"
            : "+l"(axy1), "+l"(axy2), "+l"(axy3),
              "+r"(az1), "+r"(az2), "+r"(az3),
              "+r"(ac1), "+r"(ac2), "+f"(fc3)
            : "l"(xi2), "l"(yi2), "l"(zi2),
              "l"(rA.x), "l"(rA.y), "l"(rB.x), "l"(rB.y),
              "f"(th1), "f"(th2), "f"(th3),
              "l"(rC.x), "l"(rC.y), "r"(zf0), "r"(zf1));
    }

    float* dst = g_part + (js * NSLOTS_I + slot) * 12;
    ((float4*)dst)[0] = make_float4(
        __uint_as_float((unsigned)axy1), __uint_as_float((unsigned)(axy1 >> 32)),
        __uint_as_float((unsigned)axy2), __uint_as_float((unsigned)(axy2 >> 32)));
    ((float4*)dst)[1] = make_float4(
        __uint_as_float((unsigned)axy3), __uint_as_float((unsigned)(axy3 >> 32)),
        __int_as_float(az1), __int_as_float(az2));
    ((float4*)dst)[2] = make_float4(
        __int_as_float(az3), __int_as_float(ac1),
        __int_as_float(ac2), fc3);

    // last-block finalize for this i-stripe (R8-proven protocol)
    __threadfence();
    __syncthreads();
    if (tid == 0) {
        int old = atomicAdd(&g_cnt[it * NITILE + bx], 1);
        s_last = (old == JSPLIT - 1) ? 1 : 0;
    }
    __syncthreads();
    if (!s_last) return;
    __threadfence();

    float nx = SENTC, ny = SENTC, nz = SENTC;
    if (slot < N) {
        float sx1=0,sy1=0,sx2=0,sy2=0,sx3=0,sy3=0, c3=0.f;
        int   z1=0,z2=0,z3=0, c1=0,c2=0;
        #pragma unroll 3
        for (int js2 = 0; js2 < JSPLIT; js2++) {
            const float4* p = (const float4*)(g_part + (js2 * NSLOTS_I + slot) * 12);
            float4 v0 = p[0], v1 = p[1], v2 = p[2];
            sx1 += v0.x; sy1 += v0.y; sx2 += v0.z; sy2 += v0.w;
            sx3 += v1.x; sy3 += v1.y;
            z1 += __float_as_int(v1.z); z2 += __float_as_int(v1.w);
            z3 += __float_as_int(v2.x);
            c1 += __float_as_int(v2.y); c2 += __float_as_int(v2.z); c3 += v2.w;
        }
        float sz1 = (float)z1 * (1.0f / ZSCALE);
        float sz2 = (float)z2 * (1.0f / ZSCALE);
        float sz3 = (float)z3 * (1.0f / ZSCALE);
        const float* wp = g_w + (it * N + slot) * 3;
        float e0 = wp[0], e1 = wp[1], e2 = wp[2];
        float inv = 1.0f / (e0 + e1 + e2);
        float r1 = e0 / (float)c1, r2 = e1 / (float)c2, r3 = e2 / c3;
        nx = (sx1 * r1 + sx2 * r2 + sx3 * r3) * inv;
        ny = (sy1 * r1 + sy2 * r2 + sy3 * r3) * inv;
        nz = (sz1 * r1 + sz2 * r2 + sz3 * r3) * inv;
        float* oo = out + (it * N + slot) * 3;
        oo[0] = nx; oo[1] = ny; oo[2] = nz;
    }
    if (it < ITERS - 1) write_rec(dstP, slot, nx, ny, nz);
}

// ---------------------------------------------------------------------------
// Inputs: 0:X 1:X_fea 2:W1 3:b1 4:gamma 5:beta 6:W2 7:b2   Output: [4,N,3] f32
// 6 launches: linear1, bnlogits_prep, shift x4.
// ---------------------------------------------------------------------------
extern "C" void kernel_launch(void* const* d_in, const int* in_sizes, int n_in,
                              void* d_out, int out_size) {
    const float* X     = (const float*)d_in[0];
    const float* Xfea  = (const float*)d_in[1];
    const float* W1    = (const float*)d_in[2];
    const float* b1    = (const float*)d_in[3];
    const float* gamma = (const float*)d_in[4];
    const float* beta  = (const float*)d_in[5];
    const float* W2    = (const float*)d_in[6];
    const float* b2    = (const float*)d_in[7];
    float* out = (float*)d_out;

    linear1_kernel<<<dim3((N + 127) / 128, ITERS), 128>>>(Xfea, W1, b1);     // 0
    bnlogits_prep_kernel<<<ITERS, 1024>>>(X, gamma, beta, W2, b2);           // 1
    for (int it = 0; it < ITERS; it++)                                       // 2..5
        shift_kernel<<<dim3(NITILE, JSPLIT), ITILE>>>(out, it);
}

// round 13
// speedup vs baseline: 1.9070x; 1.9070x over previous
#include <cuda_runtime.h>
#include <math.h>

// Problem constants
#define N        10000
#define DF       32
#define ITERS    4
#define JSPLIT   14             // j-range splits
#define PCHUNK   366            // packed j-pairs per split (732 j), even
#define NPAIR_PAD (JSPLIT * PCHUNK)    // 5124 pairs = 10248 j slots
#define NSLOTS_J (2 * NPAIR_PAD)       // 10248
#define ITILE    256
#define NITILE   40             // i-slots 10240; grid 40*14 = 560, 1 wave @ occ 4
#define NSLOTS_I 10240
#define ZSCALE   16384.0f
#define SENTC    1.0e6f

// Scratch (static device arrays; cudaMalloc is forbidden)
__device__ float g_pairsA[NPAIR_PAD * 12];
__device__ float g_pairsB[NPAIR_PAD * 12];
__device__ int   g_cnt[ITERS * NITILE];        // stripe completion counters
__device__ float g_part[JSPLIT * NSLOTS_I * 12];
__device__ float g_h[ITERS * N * DF];
__device__ float g_stats[ITERS * DF * 2];
__device__ float g_w[ITERS * N * 3];

// ---------------------------------------------------------------------------
// Pair record (12 words per packed j-pair):
//   [0..7]  x0 x1 y0 y1 z0 z1 nu0 nu1   (nu = -0.5|x|^2; also the addends)
//   [8,9]   round(z*2^14) s32 (zf0, zf1)
//   [10,11] pad (never read)
// ---------------------------------------------------------------------------
__device__ __forceinline__ void write_rec(float* buf, int s, float x, float y, float z) {
    int p = s >> 1, h = s & 1;
    float nu = -0.5f * (x * x + y * y + z * z);
    float* rec = buf + p * 12;
    rec[0 + h] = x;
    rec[2 + h] = y;
    rec[4 + h] = z;
    rec[6 + h] = nu;
    ((int*)rec)[8 + h] = __float2int_rn(z * ZSCALE);
}

// ---------------------------------------------------------------------------
// linear1: h = X_fea @ W1^T + b1 for all 4 iterations
// ---------------------------------------------------------------------------
__global__ void linear1_kernel(const float* __restrict__ Xfea,
                               const float* __restrict__ W1,
                               const float* __restrict__ b1) {
    int it = blockIdx.y;
    int n  = blockIdx.x * blockDim.x + threadIdx.x;
    __shared__ float sW[DF * DF];
    __shared__ float sb[DF];
    for (int k = threadIdx.x; k < DF * DF; k += blockDim.x) sW[k] = W1[it * DF * DF + k];
    if (threadIdx.x < DF) sb[threadIdx.x] = b1[it * DF + threadIdx.x];
    __syncthreads();
    if (n >= N) return;
    float xf[DF];
    const float4* xr = (const float4*)(Xfea + n * DF);
    #pragma unroll
    for (int q = 0; q < DF / 4; q++) {
        float4 v = xr[q];
        xf[4*q] = v.x; xf[4*q+1] = v.y; xf[4*q+2] = v.z; xf[4*q+3] = v.w;
    }
    float* hout = g_h + (it * N + n) * DF;
    #pragma unroll 4
    for (int f = 0; f < DF; f++) {
        float acc = sb[f];
        #pragma unroll
        for (int k = 0; k < DF; k++) acc = fmaf(xf[k], sW[f * DF + k], acc);
        hout[f] = acc;
    }
}

// BN stats + pair-record prep + counter reset (cheap, R11-proven).
__global__ void __launch_bounds__(1024, 1) bnstats_prep_kernel(const float* __restrict__ X) {
    int it = blockIdx.x;
    int tid = threadIdx.x;
    int w  = tid >> 5;
    int f  = tid & 31;
    float s = 0.f, sq = 0.f;
    for (int n = w; n < N; n += 32) {
        float v = g_h[(it * N + n) * DF + f];
        s += v;
        sq = fmaf(v, v, sq);
    }
    __shared__ float ss[32 * 33];
    __shared__ float sqq[32 * 33];
    ss [w * 33 + f] = s;
    sqq[w * 33 + f] = sq;
    __syncthreads();
    if (tid < DF) {
        float ts = 0.f, tq = 0.f;
        for (int ww = 0; ww < 32; ww++) { ts += ss[ww * 33 + f]; tq += sqq[ww * 33 + f]; }
        float mu  = ts / (float)N;
        float var = tq / (float)N - mu * mu;   // biased var (matches reference)
        g_stats[(it * DF + f) * 2 + 0] = mu;
        g_stats[(it * DF + f) * 2 + 1] = rsqrtf(var + 1e-5f);
    }
    // fused prep across the 4 blocks (gtid 0..4095)
    int gtid = blockIdx.x * 1024 + tid;
    for (int sl = gtid; sl < NSLOTS_J; sl += 4096) {
        if (sl < N) write_rec(g_pairsA, sl, X[3*sl], X[3*sl+1], X[3*sl+2]);
        else        write_rec(g_pairsA, sl, SENTC, SENTC, SENTC);
        // B-buffer tail (>= NSLOTS_I) is never rewritten by shift: fill once.
        if (sl >= NSLOTS_I) write_rec(g_pairsB, sl, SENTC, SENTC, SENTC);
    }
    if (gtid < ITERS * NITILE) g_cnt[gtid] = 0;
}

// Wide-grid logits (R11-proven; NEVER fuse into the 4-block kernel).
__global__ void logits_kernel(const float* __restrict__ gamma,
                              const float* __restrict__ beta,
                              const float* __restrict__ W2,
                              const float* __restrict__ b2) {
    int it = blockIdx.y;
    int n  = blockIdx.x * blockDim.x + threadIdx.x;
    __shared__ float sg[DF], sbe[DF], smu[DF], sis[DF], sW2[3 * DF], sb2[3];
    if (threadIdx.x < DF) {
        sg [threadIdx.x] = gamma[it * DF + threadIdx.x];
        sbe[threadIdx.x] = beta [it * DF + threadIdx.x];
        smu[threadIdx.x] = g_stats[(it * DF + threadIdx.x) * 2 + 0];
        sis[threadIdx.x] = g_stats[(it * DF + threadIdx.x) * 2 + 1];
    }
    if (threadIdx.x < 3 * DF) sW2[threadIdx.x] = W2[it * 3 * DF + threadIdx.x];
    if (threadIdx.x < 3)      sb2[threadIdx.x] = b2[it * 3 + threadIdx.x];
    __syncthreads();
    if (n >= N) return;
    const float* hrow = g_h + (it * N + n) * DF;
    float a[DF];
    #pragma unroll
    for (int f = 0; f < DF; f++) {
        float v = (hrow[f] - smu[f]) * sis[f] * sg[f] + sbe[f];
        a[f] = fmaxf(v, 0.f);
    }
    float l0 = sb2[0], l1 = sb2[1], l2 = sb2[2];
    #pragma unroll
    for (int f = 0; f < DF; f++) {
        l0 = fmaf(a[f], sW2[0 * DF + f], l0);
        l1 = fmaf(a[f], sW2[1 * DF + f], l1);
        l2 = fmaf(a[f], sW2[2 * DF + f], l2);
    }
    float m = fmaxf(l0, fmaxf(l1, l2));
    float* wout = g_w + (it * N + n) * 3;
    wout[0] = expf(l0 - m);
    wout[1] = expf(l1 - m);
    wout[2] = expf(l2 - m);
}

// ---------------------------------------------------------------------------
// Mean-shift pair loop: xy accumulation reads the dist-path register halves
// directly (scalar FADD) -> 5 loads/pair instead of 8. Fused finalize.
// ---------------------------------------------------------------------------
__global__ void __launch_bounds__(ITILE, 4) shift_kernel(float* __restrict__ out, int it) {
    __shared__ __align__(16) float sj[PCHUNK * 12];   // 17.6 KB tile
    __shared__ int s_last;

    const float* srcP = (it & 1) ? g_pairsB : g_pairsA;
    float*       dstP = (it & 1) ? g_pairsA : g_pairsB;

    int js  = blockIdx.y;
    int bx  = blockIdx.x;
    int tid = threadIdx.x;

    const float4* src = (const float4*)(srcP + js * PCHUNK * 12);
    float4* d4 = (float4*)sj;
    for (int t = tid; t < PCHUNK * 3; t += ITILE) d4[t] = src[t];
    __syncthreads();

    int slot = bx * ITILE + tid;     // < NSLOTS_I
    int pb = (slot >> 1) * 12, h = slot & 1;
    float xi  = srcP[pb + 0 + h];
    float yi  = srcP[pb + 2 + h];
    float zi  = srcP[pb + 4 + h];
    float nui = srcP[pb + 6 + h];
    // d <= bw^2  <=>  (xi.xj - 0.5|xj|^2) >= 0.5|xi|^2 - 0.5 bw^2
    float th1 = -nui - 0.02f;    // bw=0.2
    float th2 = -nui - 1.445f;   // bw=1.7
    float th3 = -nui - 5.12f;    // bw=3.2

    unsigned long long xi2, yi2, zi2;
    asm("mov.b64 %0, {%1, %1};" : "=l"(xi2) : "f"(xi));
    asm("mov.b64 %0, {%1, %1};" : "=l"(yi2) : "f"(yi));
    asm("mov.b64 %0, {%1, %1};" : "=l"(zi2) : "f"(zi));

    float sx1 = 0.f, sy1 = 0.f, sx2 = 0.f, sy2 = 0.f, sx3 = 0.f, sy3 = 0.f;
    int   az1 = 0, az2 = 0, az3 = 0;      // fixed-point z sums
    int   ac1 = 0, ac2 = 0;               // counts bands 1,2 (alu)
    float fc3 = 0.0f;                     // count band 3 (fma)

    #pragma unroll 2
    for (int p = 0; p < PCHUNK; p++) {
        const float* rec = sj + p * 12;
        unsigned long long x01  = *(const unsigned long long*)(rec + 0);
        unsigned long long y01  = *(const unsigned long long*)(rec + 2);
        unsigned long long z01  = *(const unsigned long long*)(rec + 4);
        unsigned long long nu01 = *(const unsigned long long*)(rec + 6);
        unsigned long long zf01 = *(const unsigned long long*)(rec + 8);
        int zf0 = (int)(unsigned)zf01;
        int zf1 = (int)(zf01 >> 32);
        asm("{\n\t"
            ".reg .b64  t64;\n\t"
            ".reg .f32  vl, vh, x0, x1, y0, y1;\n\t"
            ".reg .pred pl1, pl2, pl3, ph1, ph2, ph3;\n\t"
            "fma.rn.f32x2 t64, %12, %15, %18;\n\t"   // xi*xj - 0.5|xj|^2
            "fma.rn.f32x2 t64, %13, %16, t64;\n\t"
            "fma.rn.f32x2 t64, %14, %17, t64;\n\t"
            "mov.b64 {vl, vh}, t64;\n\t"
            "mov.b64 {x0, x1}, %15;\n\t"
            "mov.b64 {y0, y1}, %16;\n\t"
            "setp.ge.f32 pl1, vl, %19;\n\t"
            "setp.ge.f32 pl2, vl, %20;\n\t"
            "setp.ge.f32 pl3, vl, %21;\n\t"
            "setp.ge.f32 ph1, vh, %19;\n\t"
            "setp.ge.f32 ph2, vh, %20;\n\t"
            "setp.ge.f32 ph3, vh, %21;\n\t"
            "@pl1 add.f32 %0, %0, x0;\n\t"
            "@pl1 add.f32 %1, %1, y0;\n\t"
            "@pl1 add.s32 %6, %6, %22;\n\t"
            "@pl1 add.s32 %9, %9, 1;\n\t"
            "@pl2 add.f32 %2, %2, x0;\n\t"
            "@pl2 add.f32 %3, %3, y0;\n\t"
            "@pl2 add.s32 %7, %7, %22;\n\t"
            "@pl2 add.s32 %10, %10, 1;\n\t"
            "@pl3 add.f32 %4, %4, x0;\n\t"
            "@pl3 add.f32 %5, %5, y0;\n\t"
            "@pl3 add.s32 %8, %8, %22;\n\t"
            "@pl3 add.f32 %11, %11, 0F3F800000;\n\t"
            "@ph1 add.f32 %0, %0, x1;\n\t"
            "@ph1 add.f32 %1, %1, y1;\n\t"
            "@ph1 add.s32 %6, %6, %23;\n\t"
            "@ph1 add.s32 %9, %9, 1;\n\t"
            "@ph2 add.f32 %2, %2, x1;\n\t"
            "@ph2 add.f32 %3, %3, y1;\n\t"
            "@ph2 add.s32 %7, %7, %23;\n\t"
            "@ph2 add.s32 %10, %10, 1;\n\t"
            "@ph3 add.f32 %4, %4, x1;\n\t"
            "@ph3 add.f32 %5, %5, y1;\n\t"
            "@ph3 add.s32 %8, %8, %23;\n\t"
            "@ph3 add.f32 %11, %11, 0F3F800000;\n\t"
            "}"
            : "+f"(sx1), "+f"(sy1), "+f"(sx2), "+f"(sy2), "+f"(sx3), "+f"(sy3),
              "+r"(az1), "+r"(az2), "+r"(az3),
              "+r"(ac1), "+r"(ac2), "+f"(fc3)
            : "l"(xi2), "l"(yi2), "l"(zi2),
              "l"(x01), "l"(y01), "l"(z01), "l"(nu01),
              "f"(th1), "f"(th2), "f"(th3),
              "r"(zf0), "r"(zf1));
    }

    float* dst = g_part + (js * NSLOTS_I + slot) * 12;
    ((float4*)dst)[0] = make_float4(sx1, sy1, sx2, sy2);
    ((float4*)dst)[1] = make_float4(sx3, sy3, __int_as_float(az1), __int_as_float(az2));
    ((float4*)dst)[2] = make_float4(__int_as_float(az3), __int_as_float(ac1),
                                    __int_as_float(ac2), fc3);

    // last-block finalize for this i-stripe (R8-proven protocol)
    __threadfence();
    __syncthreads();
    if (tid == 0) {
        int old = atomicAdd(&g_cnt[it * NITILE + bx], 1);
        s_last = (old == JSPLIT - 1) ? 1 : 0;
    }
    __syncthreads();
    if (!s_last) return;
    __threadfence();

    float nx = SENTC, ny = SENTC, nz = SENTC;
    if (slot < N) {
        float sx1f=0,sy1f=0,sx2f=0,sy2f=0,sx3f=0,sy3f=0, c3=0.f;
        int   z1=0,z2=0,z3=0, c1=0,c2=0;
        #pragma unroll 2
        for (int js2 = 0; js2 < JSPLIT; js2++) {
            const float4* p = (const float4*)(g_part + (js2 * NSLOTS_I + slot) * 12);
            float4 v0 = p[0], v1 = p[1], v2 = p[2];
            sx1f += v0.x; sy1f += v0.y; sx2f += v0.z; sy2f += v0.w;
            sx3f += v1.x; sy3f += v1.y;
            z1 += __float_as_int(v1.z); z2 += __float_as_int(v1.w);
            z3 += __float_as_int(v2.x);
            c1 += __float_as_int(v2.y); c2 += __float_as_int(v2.z); c3 += v2.w;
        }
        float sz1 = (float)z1 * (1.0f / ZSCALE);
        float sz2 = (float)z2 * (1.0f / ZSCALE);
        float sz3 = (float)z3 * (1.0f / ZSCALE);
        const float* wp = g_w + (it * N + slot) * 3;
        float e0 = wp[0], e1 = wp[1], e2 = wp[2];
        float inv = 1.0f / (e0 + e1 + e2);
        float r1 = e0 / (float)c1, r2 = e1 / (float)c2, r3 = e2 / c3;
        nx = (sx1f * r1 + sx2f * r2 + sx3f * r3) * inv;
        ny = (sy1f * r1 + sy2f * r2 + sy3f * r3) * inv;
        nz = (sz1 * r1 + sz2 * r2 + sz3 * r3) * inv;
        float* oo = out + (it * N + slot) * 3;
        oo[0] = nx; oo[1] = ny; oo[2] = nz;
    }
    if (it < ITERS - 1) write_rec(dstP, slot, nx, ny, nz);
}

// ---------------------------------------------------------------------------
// Inputs: 0:X 1:X_fea 2:W1 3:b1 4:gamma 5:beta 6:W2 7:b2   Output: [4,N,3] f32
// 6 launches; shift(it=0) at index 3 (ncu capture point).
// ---------------------------------------------------------------------------
extern "C" void kernel_launch(void* const* d_in, const int* in_sizes, int n_in,
                              void* d_out, int out_size) {
    const float* X     = (const float*)d_in[0];
    const float* Xfea  = (const float*)d_in[1];
    const float* W1    = (const float*)d_in[2];
    const float* b1    = (const float*)d_in[3];
    const float* gamma = (const float*)d_in[4];
    const float* beta  = (const float*)d_in[5];
    const float* W2    = (const float*)d_in[6];
    const float* b2    = (const float*)d_in[7];
    float* out = (float*)d_out;

    linear1_kernel<<<dim3((N + 127) / 128, ITERS), 128>>>(Xfea, W1, b1);        // 0
    bnstats_prep_kernel<<<ITERS, 1024>>>(X);                                     // 1
    logits_kernel<<<dim3((N + 255) / 256, ITERS), 256>>>(gamma, beta, W2, b2);   // 2
    for (int it = 0; it < ITERS; it++)                                           // 3..6
        shift_kernel<<<dim3(NITILE, JSPLIT), ITILE>>>(out, it);
}